// round 15
// baseline (speedup 1.0000x reference)
#include <cuda_runtime.h>
#include <cuda_fp16.h>
#include <cstdint>

#define NPT   400000
#define NVOX  100000
#define EPSBN 1e-3f
#define NB0   3125      // 128-point tiles
#define NSCB  98
#define YP2   66        // Ys row pitch (words), row-major [128][66]; even -> f2 aligned
#define PA    136       // A half-pitch in pass2
#define AP    20        // X10/A row pitch (words)

// ---------------- scratch ----------------
__device__ unsigned g_vm0[NVOX * 64];   // encoded raw voxel max, layer 0
__device__ unsigned g_vm1[NVOX * 64];   // encoded raw voxel max, layer 1
__device__ float4   g_mean4[NVOX];      // xyz sums, w = count
__device__ int      g_cur[NVOX];        // seeded with block-local offsets by scan1
__device__ int      g_bsum[NSCB];
__device__ int2     g_pv[NPT];          // (perm, vinv)
__device__ float    g_bns[256];         // [0:64) s0 [64:128) q0 [128:192) s1 [192:256) q1

// ---------------- helpers ----------------
__device__ __forceinline__ unsigned encf(float f) {
    int b = __float_as_int(f);
    return (b >= 0) ? ((unsigned)b | 0x80000000u) : ~(unsigned)b;
}
__device__ __forceinline__ float decf(unsigned u) {
    int b = (u & 0x80000000u) ? (int)(u & 0x7fffffffu) : ~(int)u;
    return __int_as_float(b);
}
__device__ __forceinline__ unsigned h2u(__half2 h) {
    return *reinterpret_cast<unsigned*>(&h);
}
__device__ __forceinline__ uint32_t tf32r(float x) {
    uint32_t u;
    asm("cvt.rna.tf32.f32 %0, %1;" : "=r"(u) : "f"(x));
    return u;
}
__device__ __forceinline__ void mma16(float c[4], uint32_t a0, uint32_t a1, uint32_t a2,
                                      uint32_t a3, uint32_t b0, uint32_t b1) {
    asm volatile("mma.sync.aligned.m16n8k16.row.col.f32.f16.f16.f32 "
                 "{%0,%1,%2,%3}, {%4,%5,%6,%7}, {%8,%9}, {%0,%1,%2,%3};"
                 : "+f"(c[0]), "+f"(c[1]), "+f"(c[2]), "+f"(c[3])
                 : "r"(a0), "r"(a1), "r"(a2), "r"(a3), "r"(b0), "r"(b1));
}
__device__ __forceinline__ void mma8(float c[4], uint32_t a0, uint32_t a1, uint32_t a2,
                                     uint32_t a3, uint32_t b0, uint32_t b1) {
    asm volatile("mma.sync.aligned.m16n8k8.row.col.f32.tf32.tf32.f32 "
                 "{%0,%1,%2,%3}, {%4,%5,%6,%7}, {%8,%9}, {%0,%1,%2,%3};"
                 : "+f"(c[0]), "+f"(c[1]), "+f"(c[2]), "+f"(c[3])
                 : "r"(a0), "r"(a1), "r"(a2), "r"(a3), "r"(b0), "r"(b1));
}

// Fused segmented max + BN stats over row-major Ys[128][YP2], 128 sorted rows.
// Lane owns channels (lane, lane+32). Each (row, channel) visited exactly once.
// Boundary segments -> atomicMax on encoded uints (idempotent across replays).
__device__ __forceinline__ void segstat(const float* Ys, const int* sV,
                                        unsigned* gdst, float (*spw)[64],
                                        float (*sqw)[64], int w, int lane, int t,
                                        int boff) {
    int rbeg = w * 16, rend = rbeg + 16;
    float sA = 0.f, qA = 0.f, sB = 0.f, qB = 0.f;
    for (int r = rbeg; r < rend; r++) {
        if (r > 0 && sV[r] == sV[r - 1]) continue;
        int e = r + 1;
        while (e < 128 && sV[e] == sV[r]) e++;
        float mA = -3.4e38f, mB = -3.4e38f;
        for (int x = r; x < e; x++) {
            float a = Ys[x * YP2 + lane];
            float b = Ys[x * YP2 + lane + 32];
            mA = fmaxf(mA, a); mB = fmaxf(mB, b);
            sA += a; qA += a * a;
            sB += b; qB += b * b;
        }
        unsigned* d = gdst + (size_t)sV[r] * 64;
        unsigned eA = encf(mA), eB = encf(mB);
        if (r == 0 || e == 128) {
            atomicMax(d + lane, eA);
            atomicMax(d + lane + 32, eB);
        } else {
            d[lane] = eA;
            d[lane + 32] = eB;
        }
    }
    spw[w][lane] = sA; spw[w][lane + 32] = sB;
    sqw[w][lane] = qA; sqw[w][lane + 32] = qB;
    __syncthreads();
    if (t < 64) {
        float s = 0.f, q = 0.f;
#pragma unroll
        for (int k = 0; k < 8; k++) { s += spw[k][t]; q += sqw[k][t]; }
        atomicAdd(&g_bns[boff + t], s);
        atomicAdd(&g_bns[boff + 64 + t], q);
    }
}

// D-fragment spill, row-major, STS.64 per channel pair
__device__ __forceinline__ void spill(float* Ys, const float acc[8][4],
                                      int m0, int g, int q) {
#pragma unroll
    for (int tt = 0; tt < 8; tt++) {
        int n = tt * 8 + q * 2;
        *(float2*)&Ys[(m0 + g) * YP2 + n]     = make_float2(acc[tt][0], acc[tt][1]);
        *(float2*)&Ys[(m0 + g + 8) * YP2 + n] = make_float2(acc[tt][2], acc[tt][3]);
    }
}

// Build the 10-feature row for point (base+t), tf32-rounded, row-major pitch AP.
// IDENTICAL in pass1 & pass2 -> bitwise-consistent y0 across passes.
__device__ __forceinline__ void build_a(float* A, int* sV, int base, int t,
                                        const float* __restrict__ feat,
                                        const int* __restrict__ coors) {
    int2 pv = g_pv[base + t];
    int p = pv.x, v = pv.y;
    sV[t] = v;
    float4 f = reinterpret_cast<const float4*>(feat)[p];
    float4 m = g_mean4[v];
    float ic = 1.f / m.w;
    int4 co = reinterpret_cast<const int4*>(coors)[v];
    float cx = (float)co.w * 0.2f + 0.1f;
    float cy = (float)co.z * 0.2f + 0.1f - 40.f;
    float cz = (float)co.y * 4.0f + 2.0f - 3.f;
    float xs[10] = {f.x, f.y, f.z,
                    f.x - m.x * ic, f.y - m.y * ic, f.z - m.z * ic,
                    f.x - cx, f.y - cy, f.z - cz, f.w};
    float* row = A + t * AP;
#pragma unroll
    for (int k = 0; k < 10; k++) row[k] = __uint_as_float(tf32r(xs[k]));
#pragma unroll
    for (int k = 10; k < 16; k++) row[k] = 0.f;
}

// Stage W0 tf32 B-fragments
__device__ __forceinline__ void stage_wf0(float2* Wf0, const float* __restrict__ W0,
                                          int t) {
#pragma unroll
    for (int it = 0; it < 2; it++) {
        int idx = it * 256 + t;
        int ln = idx & 31, st = idx >> 5;
        int s = st >> 3, tt = st & 7;
        int n = tt * 8 + (ln >> 2);
        int k = s * 8 + (ln & 3);
        float b0 = (k < 10) ? W0[n * 10 + k] : 0.f;
        float b1 = (k + 4 < 10) ? W0[n * 10 + k + 4] : 0.f;
        Wf0[idx] = make_float2(__uint_as_float(tf32r(b0)), __uint_as_float(tf32r(b1)));
    }
}

// y0 fragments via tf32 MMA: warp owns rows [m0, m0+16), all 64 channels.
__device__ __forceinline__ void gemm0_mma(const float* A, const float2* Wf0,
                                          int m0, int g, int q, int lane,
                                          float acc[8][4]) {
#pragma unroll
    for (int s = 0; s < 2; s++) {
        int k0 = s * 8;
        uint32_t a0 = __float_as_uint(A[(m0 + g) * AP + k0 + q]);
        uint32_t a1 = __float_as_uint(A[(m0 + g + 8) * AP + k0 + q]);
        uint32_t a2 = __float_as_uint(A[(m0 + g) * AP + k0 + q + 4]);
        uint32_t a3 = __float_as_uint(A[(m0 + g + 8) * AP + k0 + q + 4]);
#pragma unroll
        for (int tt = 0; tt < 8; tt++) {
            float2 b = Wf0[(s * 8 + tt) * 32 + lane];
            mma8(acc[tt], a0, a1, a2, a3, __float_as_uint(b.x), __float_as_uint(b.y));
        }
    }
}

// per-block BN finalize from g_bns
__device__ __forceinline__ void bn_finalize(int boff, const float* __restrict__ gamma,
                                            const float* __restrict__ beta,
                                            float* sSc, float* sSh, int t) {
    if (t < 64) {
        double mu = (double)g_bns[boff + t] / (double)NPT;
        double var = (double)g_bns[boff + 64 + t] / (double)NPT - mu * mu;
        float sc = gamma[t] * rsqrtf((float)var + EPSBN);
        sSc[t] = sc;
        sSh[t] = beta[t] - (float)mu * sc;
    }
}

// ---------------- hist: count + xyz sums (single vector RED) ----------------
__global__ void k_hist(const float* __restrict__ feat, const int* __restrict__ inv) {
    int p = blockIdx.x * blockDim.x + threadIdx.x;
    if (p >= NPT) return;
    float4 f = reinterpret_cast<const float4*>(feat)[p];
    int v = inv[p];
    asm volatile("red.global.add.v4.f32 [%0], {%1, %2, %3, %4};"
                 :: "l"(&g_mean4[v]), "f"(f.x), "f"(f.y), "f"(f.z), "f"(1.0f)
                 : "memory");
}

// counts scan (warp-shuffle); seeds g_cur with the BLOCK-LOCAL exclusive offset
// (overwrite -> deterministic across replays). Global prefix added in k_scatter.
__global__ __launch_bounds__(1024) void k_scan1() {
    __shared__ int wsum[32];
    int i = blockIdx.x * 1024 + threadIdx.x;
    int v = (i < NVOX) ? (int)g_mean4[i].w : 0;
    int lane = threadIdx.x & 31, wid = threadIdx.x >> 5;
    int x = v;
#pragma unroll
    for (int d = 1; d < 32; d <<= 1) {
        int y = __shfl_up_sync(0xffffffffu, x, d);
        if (lane >= d) x += y;
    }
    if (lane == 31) wsum[wid] = x;
    __syncthreads();
    if (wid == 0) {
        int y = wsum[lane];
#pragma unroll
        for (int d = 1; d < 32; d <<= 1) {
            int z = __shfl_up_sync(0xffffffffu, y, d);
            if (lane >= d) y += z;
        }
        wsum[lane] = y;
    }
    __syncthreads();
    int pre = (wid > 0) ? wsum[wid - 1] : 0;
    if (i < NVOX) g_cur[i] = pre + x - v;
    if (threadIdx.x == 1023) g_bsum[blockIdx.x] = pre + x;
}

// scatter, 4 points/thread: single atomic per point (g_cur pre-seeded with
// local offset) + smem-scanned 98-block prefix; zeroes g_bns for the passes
__global__ __launch_bounds__(256) void k_scatter(const int* __restrict__ inv) {
    __shared__ int pre[128];
    int t = threadIdx.x;
    if (t < 128) pre[t] = (t < NSCB) ? g_bsum[t] : 0;
    __syncthreads();
    for (int d = 1; d < 128; d <<= 1) {
        int x = (t >= d && t < 128) ? pre[t - d] : 0;
        __syncthreads();
        if (t < 128) pre[t] += x;
        __syncthreads();
    }
    int i = blockIdx.x * blockDim.x + t;
    if (i < 256) g_bns[i] = 0.f;       // reset BN accumulators for this replay
    int p0 = i * 4;
    if (p0 >= NPT) return;
    int4 vv = ((const int4*)inv)[i];
    int r0 = atomicAdd(&g_cur[vv.x], 1);
    int r1 = atomicAdd(&g_cur[vv.y], 1);
    int r2 = atomicAdd(&g_cur[vv.z], 1);
    int r3 = atomicAdd(&g_cur[vv.w], 1);
    int b0 = vv.x >> 10, b1 = vv.y >> 10, b2 = vv.z >> 10, b3 = vv.w >> 10;
    g_pv[r0 + (b0 ? pre[b0 - 1] : 0)] = make_int2(p0 + 0, vv.x);
    g_pv[r1 + (b1 ? pre[b1 - 1] : 0)] = make_int2(p0 + 1, vv.y);
    g_pv[r2 + (b2 ? pre[b2 - 1] : 0)] = make_int2(p0 + 2, vv.z);
    g_pv[r3 + (b3 ? pre[b3 - 1] : 0)] = make_int2(p0 + 3, vv.w);
}

// ---------------- pass1: y0 via tf32 MMA -> stats + raw voxel max ----------------
// smem union: [A float[128*AP] | Wf0 float2[512]] overlaid by Ys[128*YP2]
__global__ __launch_bounds__(256) void k_pass1(const float* __restrict__ feat,
                                               const int* __restrict__ coors,
                                               const float* __restrict__ W0) {
    __shared__ float S[128 * YP2];      // 8448 floats >= 2560 (A) + 1024 (Wf0)
    __shared__ int   sV[128];
    __shared__ float sp[8][64], sq[8][64];
    float*  A   = S;
    float2* Wf0 = (float2*)(S + 128 * AP);
    float*  Ys  = S;
    int t = threadIdx.x, lane = t & 31, w = t >> 5;
    int base = blockIdx.x * 128;
    if (t < 128) build_a(A, sV, base, t, feat, coors);
    stage_wf0(Wf0, W0, t);
    __syncthreads();
    int g = lane >> 2, q = lane & 3, m0 = w * 16;
    float acc[8][4] = {};
    gemm0_mma(A, Wf0, m0, g, q, lane, acc);
    __syncthreads();   // A/Wf0 dead -> Ys overlay safe
    spill(Ys, acc, m0, g, q);
    __syncthreads();
    segstat(Ys, sV, g_vm0, sp, sq, w, lane, t, 0);
}

// ---------------- pass2: h0 via tf32 MMA, inline v0, fp16 MMA, fused epilogue ----------------
// dyn smem (bytes):
//   [0, 34816)      Ah half[128][PA]  (overlaid by Ys[128][YP2] floats after main MMA: 33792B)
//   [34816, 51200)  Wf uint2[2048]    (W1 fp16 fragments)
//   [51200, 61440)  A float[128*AP]   (tf32 X10)
//   [61440, 65536)  Wf0 float2[512]   (W0 tf32 fragments)
#define P2_DSM 65536
__global__ __launch_bounds__(256, 3) void k_pass2(const float* __restrict__ feat,
                                                  const int* __restrict__ coors,
                                                  const float* __restrict__ W0,
                                                  const float* __restrict__ W1,
                                                  const float* __restrict__ gamma0,
                                                  const float* __restrict__ beta0) {
    extern __shared__ char dsm[];
    __half* Ah  = (__half*)dsm;
    uint2*  Wf  = (uint2*)(dsm + 34816);
    float*  A   = (float*)(dsm + 51200);
    float2* Wf0 = (float2*)(dsm + 61440);
    float*  Ys  = (float*)dsm;
    __shared__ int   sV[128];
    __shared__ float sSc[64], sSh[64];
    __shared__ float sp[8][64], sq[8][64];

    int t = threadIdx.x, lane = t & 31, w = t >> 5;
    int base = blockIdx.x * 128;

    if (t < 128) build_a(A, sV, base, t, feat, coors);
    bn_finalize(0, gamma0, beta0, sSc, sSh, t);
    stage_wf0(Wf0, W0, t);
    // W1 fp16 B fragments: Wf[(s*8+tt)*32+ln] = {h2(B[k..k+1][n]), h2(B[k+8..k+9][n])}
#pragma unroll
    for (int it = 0; it < 8; it++) {
        int idx = it * 256 + t;
        int ln = idx & 31, st = idx >> 5;
        int s = st >> 3, tt = st & 7;
        int n = tt * 8 + (ln >> 2);
        int k = s * 16 + (ln & 3) * 2;
        const float* wr = &W1[n * 128 + k];
        __half2 b0 = __floats2half2_rn(wr[0], wr[1]);
        __half2 b1 = __floats2half2_rn(wr[8], wr[9]);
        Wf[idx] = make_uint2(h2u(b0), h2u(b1));
    }
    __syncthreads();

    // v0 half of Ah (k=64..127): decode vm0, BN0+ReLU (monotone), fp16
#pragma unroll
    for (int it = 0; it < 8; it++) {
        int idx = it * 256 + t;
        int m = idx >> 4, c4 = (idx & 15) * 4;
        uint4 u = *(const uint4*)&g_vm0[(size_t)sV[m] * 64 + c4];
        float f0 = fmaxf(fmaf(decf(u.x), sSc[c4 + 0], sSh[c4 + 0]), 0.f);
        float f1 = fmaxf(fmaf(decf(u.y), sSc[c4 + 1], sSh[c4 + 1]), 0.f);
        float f2 = fmaxf(fmaf(decf(u.z), sSc[c4 + 2], sSh[c4 + 2]), 0.f);
        float f3 = fmaxf(fmaf(decf(u.w), sSc[c4 + 3], sSh[c4 + 3]), 0.f);
        *(uint2*)&Ah[m * PA + 64 + c4] = make_uint2(h2u(__floats2half2_rn(f0, f1)),
                                                    h2u(__floats2half2_rn(f2, f3)));
    }
    // h0 half of Ah (k=0..63): y0 via tf32 MMA (bitwise = pass1), BN0+ReLU, fp16
    int g = lane >> 2, q = lane & 3, m0 = w * 16;
    {
        float acc0[8][4] = {};
        gemm0_mma(A, Wf0, m0, g, q, lane, acc0);
#pragma unroll
        for (int tt = 0; tt < 8; tt++) {
            int n = tt * 8 + q * 2;
            float h00 = fmaxf(fmaf(acc0[tt][0], sSc[n],     sSh[n]),     0.f);
            float h01 = fmaxf(fmaf(acc0[tt][1], sSc[n + 1], sSh[n + 1]), 0.f);
            float h10 = fmaxf(fmaf(acc0[tt][2], sSc[n],     sSh[n]),     0.f);
            float h11 = fmaxf(fmaf(acc0[tt][3], sSc[n + 1], sSh[n + 1]), 0.f);
            *(unsigned*)&Ah[(m0 + g) * PA + n]     = h2u(__floats2half2_rn(h00, h01));
            *(unsigned*)&Ah[(m0 + g + 8) * PA + n] = h2u(__floats2half2_rn(h10, h11));
        }
    }
    __syncthreads();

    // fp16 MMA via ldmatrix: warp w -> rows [w*16, w*16+16), all 64 n
    uint32_t lmaddr = (uint32_t)__cvta_generic_to_shared(
        &Ah[(m0 + (lane & 7) + (lane & 8)) * PA + (lane >> 4) * 8]);
    float acc[8][4] = {};
#pragma unroll
    for (int s = 0; s < 8; s++) {
        uint32_t a0, a1, a2, a3;
        asm volatile("ldmatrix.sync.aligned.m8n8.x4.shared.b16 {%0,%1,%2,%3}, [%4];"
                     : "=r"(a0), "=r"(a1), "=r"(a2), "=r"(a3)
                     : "r"(lmaddr + s * 32));
#pragma unroll
        for (int tt = 0; tt < 8; tt++) {
            uint2 b = Wf[(s * 8 + tt) * 32 + lane];
            mma16(acc[tt], a0, a1, a2, a3, b.x, b.y);
        }
    }
    __syncthreads();   // Ah dead -> Ys overlay safe
    spill(Ys, acc, m0, g, q);
    __syncthreads();
    segstat(Ys, sV, g_vm1, sp, sq, w, lane, t, 128);
}

// out = relu(sc1 * rawmax + sh1), vectorized, + coors tail; re-zero g_mean4
__global__ __launch_bounds__(256) void k_outfin(const int* __restrict__ coors,
                                                const float* __restrict__ gamma1,
                                                const float* __restrict__ beta1,
                                                float* __restrict__ out,
                                                int out_n, int do_coors) {
    __shared__ float sSc[64], sSh[64];
    int t = threadIdx.x;
    bn_finalize(128, gamma1, beta1, sSc, sSh, t);
    __syncthreads();
    int i4 = blockIdx.x * blockDim.x + t;
    if (i4 < NVOX) g_mean4[i4] = make_float4(0.f, 0.f, 0.f, 0.f);  // for next replay's hist
    if (i4 < NVOX * 16) {
        uint4 u = *(const uint4*)&g_vm1[(size_t)i4 * 4];
        int c = (i4 * 4) & 63;
        float4 r;
        r.x = fmaxf(fmaf(decf(u.x), sSc[c + 0], sSh[c + 0]), 0.f);
        r.y = fmaxf(fmaf(decf(u.y), sSc[c + 1], sSh[c + 1]), 0.f);
        r.z = fmaxf(fmaf(decf(u.z), sSc[c + 2], sSh[c + 2]), 0.f);
        r.w = fmaxf(fmaf(decf(u.w), sSc[c + 3], sSh[c + 3]), 0.f);
        if (i4 * 4 + 3 < out_n) {
            *(float4*)&out[(size_t)i4 * 4] = r;
        } else {
            if (i4 * 4 + 0 < out_n) out[i4 * 4 + 0] = r.x;
            if (i4 * 4 + 1 < out_n) out[i4 * 4 + 1] = r.y;
            if (i4 * 4 + 2 < out_n) out[i4 * 4 + 2] = r.z;
            if (i4 * 4 + 3 < out_n) out[i4 * 4 + 3] = r.w;
        }
    } else if (do_coors) {
        int j4 = i4 - NVOX * 16;
        if (j4 < NVOX) {
            int4 cc = ((const int4*)coors)[j4];
            float4 r = {(float)cc.x, (float)cc.y, (float)cc.z, (float)cc.w};
            *(float4*)&out[NVOX * 64 + (size_t)j4 * 4] = r;
        }
    }
}

// ---------------- launch ----------------
extern "C" void kernel_launch(void* const* d_in, const int* in_sizes, int n_in,
                              void* d_out, int out_size) {
    const float* feat   = (const float*)d_in[0];
    const float* W0     = (const float*)d_in[1];
    const float* gamma0 = (const float*)d_in[2];
    const float* beta0  = (const float*)d_in[3];
    const float* W1     = (const float*)d_in[4];
    const float* gamma1 = (const float*)d_in[5];
    const float* beta1  = (const float*)d_in[6];
    const int*   inv    = (const int*)d_in[7];
    const int*   coors  = (const int*)d_in[8];
    float* out = (float*)d_out;

    cudaFuncSetAttribute(k_pass2, cudaFuncAttributeMaxDynamicSharedMemorySize, P2_DSM);

    k_hist<<<(NPT + 255) / 256, 256>>>(feat, inv);
    k_scan1<<<NSCB, 1024>>>();
    k_scatter<<<(NPT / 4 + 255) / 256, 256>>>(inv);

    k_pass1<<<NB0, 256>>>(feat, coors, W0);
    k_pass2<<<NB0, 256, P2_DSM>>>(feat, coors, W0, W1, gamma0, beta0);

    int do_coors = (out_size >= NVOX * 64 + NVOX * 4) ? 1 : 0;
    k_outfin<<<(NVOX * 17 + 255) / 256, 256>>>(coors, gamma1, beta1, out, out_size, do_coors);
}

// round 16
// speedup vs baseline: 1.0573x; 1.0573x over previous
#include <cuda_runtime.h>
#include <cuda_fp16.h>
#include <cstdint>

#define NPT   400000
#define NVOX  100000
#define EPSBN 1e-3f
#define NB0   3125      // 128-point tiles
#define NSCB  98
#define YP    133       // Ys pitch (odd word stride -> conflict-free column reads)
#define PA    136       // A half-pitch in pass2
#define AP    20        // X10/A row pitch (words)

// ---------------- scratch ----------------
__device__ unsigned g_vm0[NVOX * 64];   // encoded raw voxel max, layer 0
__device__ unsigned g_vm1[NVOX * 64];   // encoded raw voxel max, layer 1
__device__ float4   g_mean4[NVOX];      // xyz sums, w = count
__device__ int      g_cur[NVOX];        // seeded with block-local offsets by scan1
__device__ int      g_bsum[NSCB];
__device__ int2     g_pv[NPT];          // (perm, vinv)
__device__ float    g_bns[256];         // [0:64) s0 [64:128) q0 [128:192) s1 [192:256) q1

// ---------------- helpers ----------------
__device__ __forceinline__ unsigned encf(float f) {
    int b = __float_as_int(f);
    return (b >= 0) ? ((unsigned)b | 0x80000000u) : ~(unsigned)b;
}
__device__ __forceinline__ float decf(unsigned u) {
    int b = (u & 0x80000000u) ? (int)(u & 0x7fffffffu) : ~(int)u;
    return __int_as_float(b);
}
__device__ __forceinline__ unsigned h2u(__half2 h) {
    return *reinterpret_cast<unsigned*>(&h);
}
__device__ __forceinline__ uint32_t tf32r(float x) {
    uint32_t u;
    asm("cvt.rna.tf32.f32 %0, %1;" : "=r"(u) : "f"(x));
    return u;
}
__device__ __forceinline__ void mma16(float c[4], uint32_t a0, uint32_t a1, uint32_t a2,
                                      uint32_t a3, uint32_t b0, uint32_t b1) {
    asm volatile("mma.sync.aligned.m16n8k16.row.col.f32.f16.f16.f32 "
                 "{%0,%1,%2,%3}, {%4,%5,%6,%7}, {%8,%9}, {%0,%1,%2,%3};"
                 : "+f"(c[0]), "+f"(c[1]), "+f"(c[2]), "+f"(c[3])
                 : "r"(a0), "r"(a1), "r"(a2), "r"(a3), "r"(b0), "r"(b1));
}
__device__ __forceinline__ void mma8(float c[4], uint32_t a0, uint32_t a1, uint32_t a2,
                                     uint32_t a3, uint32_t b0, uint32_t b1) {
    asm volatile("mma.sync.aligned.m16n8k8.row.col.f32.tf32.tf32.f32 "
                 "{%0,%1,%2,%3}, {%4,%5,%6,%7}, {%8,%9}, {%0,%1,%2,%3};"
                 : "+f"(c[0]), "+f"(c[1]), "+f"(c[2]), "+f"(c[3])
                 : "r"(a0), "r"(a1), "r"(a2), "r"(a3), "r"(b0), "r"(b1));
}

// Fused segmented max + BN stats over channel-major Ys[64][YP], 128 sorted rows.
// Each (row, channel) is visited exactly once. Boundary segments -> atomicMax
// on encoded uints (idempotent across graph replays). Interior -> plain store.
__device__ __forceinline__ void segstat(const float* Ys, const int* sV,
                                        unsigned* gdst, float (*spw)[64],
                                        float (*sqw)[64], int w, int lane, int t,
                                        int boff) {
    int rbeg = w * 16, rend = rbeg + 16;
    float sA = 0.f, qA = 0.f, sB = 0.f, qB = 0.f;
    for (int r = rbeg; r < rend; r++) {
        if (r > 0 && sV[r] == sV[r - 1]) continue;
        int e = r + 1;
        while (e < 128 && sV[e] == sV[r]) e++;
        float mA = -3.4e38f, mB = -3.4e38f;
        for (int x = r; x < e; x++) {
            float a = Ys[lane * YP + x];
            float b = Ys[(lane + 32) * YP + x];
            mA = fmaxf(mA, a); mB = fmaxf(mB, b);
            sA += a; qA += a * a;
            sB += b; qB += b * b;
        }
        unsigned* d = gdst + (size_t)sV[r] * 64;
        unsigned eA = encf(mA), eB = encf(mB);
        if (r == 0 || e == 128) {
            atomicMax(d + lane, eA);
            atomicMax(d + lane + 32, eB);
        } else {
            d[lane] = eA;
            d[lane + 32] = eB;
        }
    }
    spw[w][lane] = sA; spw[w][lane + 32] = sB;
    sqw[w][lane] = qA; sqw[w][lane + 32] = qB;
    __syncthreads();
    if (t < 64) {
        float s = 0.f, q = 0.f;
#pragma unroll
        for (int k = 0; k < 8; k++) { s += spw[k][t]; q += sqw[k][t]; }
        atomicAdd(&g_bns[boff + t], s);
        atomicAdd(&g_bns[boff + 64 + t], q);
    }
}

// D-fragment spill, channel-major
__device__ __forceinline__ void spill(float* Ys, const float acc[8][4],
                                      int m0, int g, int q) {
#pragma unroll
    for (int tt = 0; tt < 8; tt++) {
        int n = tt * 8 + q * 2;
        Ys[(n + 0) * YP + m0 + g]     = acc[tt][0];
        Ys[(n + 1) * YP + m0 + g]     = acc[tt][1];
        Ys[(n + 0) * YP + m0 + g + 8] = acc[tt][2];
        Ys[(n + 1) * YP + m0 + g + 8] = acc[tt][3];
    }
}

// Build the 10-feature row for point (base+t), tf32-rounded, row-major pitch AP.
// IDENTICAL in pass1 & pass2 -> bitwise-consistent y0 across passes.
__device__ __forceinline__ void build_a(float* A, int* sV, int base, int t,
                                        const float* __restrict__ feat,
                                        const int* __restrict__ coors) {
    int2 pv = g_pv[base + t];
    int p = pv.x, v = pv.y;
    sV[t] = v;
    float4 f = reinterpret_cast<const float4*>(feat)[p];
    float4 m = g_mean4[v];
    float ic = 1.f / m.w;
    int4 co = reinterpret_cast<const int4*>(coors)[v];
    float cx = (float)co.w * 0.2f + 0.1f;
    float cy = (float)co.z * 0.2f + 0.1f - 40.f;
    float cz = (float)co.y * 4.0f + 2.0f - 3.f;
    float xs[10] = {f.x, f.y, f.z,
                    f.x - m.x * ic, f.y - m.y * ic, f.z - m.z * ic,
                    f.x - cx, f.y - cy, f.z - cz, f.w};
    float* row = A + t * AP;
#pragma unroll
    for (int k = 0; k < 10; k++) row[k] = __uint_as_float(tf32r(xs[k]));
#pragma unroll
    for (int k = 10; k < 16; k++) row[k] = 0.f;
}

// Stage W0 tf32 B-fragments
__device__ __forceinline__ void stage_wf0(float2* Wf0, const float* __restrict__ W0,
                                          int t) {
#pragma unroll
    for (int it = 0; it < 2; it++) {
        int idx = it * 256 + t;
        int ln = idx & 31, st = idx >> 5;
        int s = st >> 3, tt = st & 7;
        int n = tt * 8 + (ln >> 2);
        int k = s * 8 + (ln & 3);
        float b0 = (k < 10) ? W0[n * 10 + k] : 0.f;
        float b1 = (k + 4 < 10) ? W0[n * 10 + k + 4] : 0.f;
        Wf0[idx] = make_float2(__uint_as_float(tf32r(b0)), __uint_as_float(tf32r(b1)));
    }
}

// y0 fragments via tf32 MMA: warp owns rows [m0, m0+16), all 64 channels.
__device__ __forceinline__ void gemm0_mma(const float* A, const float2* Wf0,
                                          int m0, int g, int q, int lane,
                                          float acc[8][4]) {
#pragma unroll
    for (int s = 0; s < 2; s++) {
        int k0 = s * 8;
        uint32_t a0 = __float_as_uint(A[(m0 + g) * AP + k0 + q]);
        uint32_t a1 = __float_as_uint(A[(m0 + g + 8) * AP + k0 + q]);
        uint32_t a2 = __float_as_uint(A[(m0 + g) * AP + k0 + q + 4]);
        uint32_t a3 = __float_as_uint(A[(m0 + g + 8) * AP + k0 + q + 4]);
#pragma unroll
        for (int tt = 0; tt < 8; tt++) {
            float2 b = Wf0[(s * 8 + tt) * 32 + lane];
            mma8(acc[tt], a0, a1, a2, a3, __float_as_uint(b.x), __float_as_uint(b.y));
        }
    }
}

// per-block BN finalize from g_bns
__device__ __forceinline__ void bn_finalize(int boff, const float* __restrict__ gamma,
                                            const float* __restrict__ beta,
                                            float* sSc, float* sSh, int t) {
    if (t < 64) {
        double mu = (double)g_bns[boff + t] / (double)NPT;
        double var = (double)g_bns[boff + 64 + t] / (double)NPT - mu * mu;
        float sc = gamma[t] * rsqrtf((float)var + EPSBN);
        sSc[t] = sc;
        sSh[t] = beta[t] - (float)mu * sc;
    }
}

// ---------------- hist: count + xyz sums (single vector RED) ----------------
__global__ void k_hist(const float* __restrict__ feat, const int* __restrict__ inv) {
    int p = blockIdx.x * blockDim.x + threadIdx.x;
    if (p >= NPT) return;
    float4 f = reinterpret_cast<const float4*>(feat)[p];
    int v = inv[p];
    asm volatile("red.global.add.v4.f32 [%0], {%1, %2, %3, %4};"
                 :: "l"(&g_mean4[v]), "f"(f.x), "f"(f.y), "f"(f.z), "f"(1.0f)
                 : "memory");
}

// counts scan (warp-shuffle); seeds g_cur with the BLOCK-LOCAL exclusive offset
// (overwrite -> deterministic across replays). Global prefix added in k_scatter.
__global__ __launch_bounds__(1024) void k_scan1() {
    __shared__ int wsum[32];
    int i = blockIdx.x * 1024 + threadIdx.x;
    int v = (i < NVOX) ? (int)g_mean4[i].w : 0;
    int lane = threadIdx.x & 31, wid = threadIdx.x >> 5;
    int x = v;
#pragma unroll
    for (int d = 1; d < 32; d <<= 1) {
        int y = __shfl_up_sync(0xffffffffu, x, d);
        if (lane >= d) x += y;
    }
    if (lane == 31) wsum[wid] = x;
    __syncthreads();
    if (wid == 0) {
        int y = wsum[lane];
#pragma unroll
        for (int d = 1; d < 32; d <<= 1) {
            int z = __shfl_up_sync(0xffffffffu, y, d);
            if (lane >= d) y += z;
        }
        wsum[lane] = y;
    }
    __syncthreads();
    int pre = (wid > 0) ? wsum[wid - 1] : 0;
    if (i < NVOX) g_cur[i] = pre + x - v;
    if (threadIdx.x == 1023) g_bsum[blockIdx.x] = pre + x;
}

// scatter, 4 points/thread: single atomic per point (g_cur pre-seeded with
// local offset) + smem-scanned 98-block prefix; zeroes g_bns for the passes
__global__ __launch_bounds__(256) void k_scatter(const int* __restrict__ inv) {
    __shared__ int pre[128];
    int t = threadIdx.x;
    if (t < 128) pre[t] = (t < NSCB) ? g_bsum[t] : 0;
    __syncthreads();
    for (int d = 1; d < 128; d <<= 1) {
        int x = (t >= d && t < 128) ? pre[t - d] : 0;
        __syncthreads();
        if (t < 128) pre[t] += x;
        __syncthreads();
    }
    int i = blockIdx.x * blockDim.x + t;
    if (i < 256) g_bns[i] = 0.f;       // reset BN accumulators for this replay
    int p0 = i * 4;
    if (p0 >= NPT) return;
    int4 vv = ((const int4*)inv)[i];
    int r0 = atomicAdd(&g_cur[vv.x], 1);
    int r1 = atomicAdd(&g_cur[vv.y], 1);
    int r2 = atomicAdd(&g_cur[vv.z], 1);
    int r3 = atomicAdd(&g_cur[vv.w], 1);
    int b0 = vv.x >> 10, b1 = vv.y >> 10, b2 = vv.z >> 10, b3 = vv.w >> 10;
    g_pv[r0 + (b0 ? pre[b0 - 1] : 0)] = make_int2(p0 + 0, vv.x);
    g_pv[r1 + (b1 ? pre[b1 - 1] : 0)] = make_int2(p0 + 1, vv.y);
    g_pv[r2 + (b2 ? pre[b2 - 1] : 0)] = make_int2(p0 + 2, vv.z);
    g_pv[r3 + (b3 ? pre[b3 - 1] : 0)] = make_int2(p0 + 3, vv.w);
}

// ---------------- pass1: y0 via tf32 MMA -> stats + raw voxel max ----------------
// smem union: [A float[128*AP] | Wf0 float2[512]] overlaid by Ys[64*YP]
__global__ __launch_bounds__(256) void k_pass1(const float* __restrict__ feat,
                                               const int* __restrict__ coors,
                                               const float* __restrict__ W0) {
    __shared__ float S[64 * YP];        // 8512 floats >= 2560 (A) + 1024 (Wf0)
    __shared__ int   sV[128];
    __shared__ float sp[8][64], sq[8][64];
    float*  A   = S;
    float2* Wf0 = (float2*)(S + 128 * AP);
    float*  Ys  = S;
    int t = threadIdx.x, lane = t & 31, w = t >> 5;
    int base = blockIdx.x * 128;
    if (t < 128) build_a(A, sV, base, t, feat, coors);
    stage_wf0(Wf0, W0, t);
    __syncthreads();
    int g = lane >> 2, q = lane & 3, m0 = w * 16;
    float acc[8][4] = {};
    gemm0_mma(A, Wf0, m0, g, q, lane, acc);
    __syncthreads();   // A/Wf0 dead -> Ys overlay safe
    spill(Ys, acc, m0, g, q);
    __syncthreads();
    segstat(Ys, sV, g_vm0, sp, sq, w, lane, t, 0);
}

// ---------------- pass2: h0 via tf32 MMA, inline v0, fp16 MMA, fused epilogue ----------------
// dyn smem (bytes):
//   [0, 34816)      Ah half[128][PA]  (overlaid by Ys[64][YP] floats after main MMA)
//   [34816, 51200)  Wf uint2[2048]    (W1 fp16 fragments)
//   [51200, 61440)  A float[128*AP]   (tf32 X10)
//   [61440, 65536)  Wf0 float2[512]   (W0 tf32 fragments)
#define P2_DSM 65536
__global__ __launch_bounds__(256, 3) void k_pass2(const float* __restrict__ feat,
                                                  const int* __restrict__ coors,
                                                  const float* __restrict__ W0,
                                                  const float* __restrict__ W1,
                                                  const float* __restrict__ gamma0,
                                                  const float* __restrict__ beta0) {
    extern __shared__ char dsm[];
    __half* Ah  = (__half*)dsm;
    uint2*  Wf  = (uint2*)(dsm + 34816);
    float*  A   = (float*)(dsm + 51200);
    float2* Wf0 = (float2*)(dsm + 61440);
    float*  Ys  = (float*)dsm;
    __shared__ int   sV[128];
    __shared__ float sSc[64], sSh[64];
    __shared__ float sp[8][64], sq[8][64];

    int t = threadIdx.x, lane = t & 31, w = t >> 5;
    int base = blockIdx.x * 128;

    if (t < 128) build_a(A, sV, base, t, feat, coors);
    bn_finalize(0, gamma0, beta0, sSc, sSh, t);
    stage_wf0(Wf0, W0, t);
    // W1 fp16 B fragments: Wf[(s*8+tt)*32+ln] = {h2(B[k..k+1][n]), h2(B[k+8..k+9][n])}
#pragma unroll
    for (int it = 0; it < 8; it++) {
        int idx = it * 256 + t;
        int ln = idx & 31, st = idx >> 5;
        int s = st >> 3, tt = st & 7;
        int n = tt * 8 + (ln >> 2);
        int k = s * 16 + (ln & 3) * 2;
        const float* wr = &W1[n * 128 + k];
        __half2 b0 = __floats2half2_rn(wr[0], wr[1]);
        __half2 b1 = __floats2half2_rn(wr[8], wr[9]);
        Wf[idx] = make_uint2(h2u(b0), h2u(b1));
    }
    __syncthreads();

    // v0 half of Ah (k=64..127): decode vm0, BN0+ReLU (monotone), fp16
#pragma unroll
    for (int it = 0; it < 8; it++) {
        int idx = it * 256 + t;
        int m = idx >> 4, c4 = (idx & 15) * 4;
        uint4 u = *(const uint4*)&g_vm0[(size_t)sV[m] * 64 + c4];
        float f0 = fmaxf(fmaf(decf(u.x), sSc[c4 + 0], sSh[c4 + 0]), 0.f);
        float f1 = fmaxf(fmaf(decf(u.y), sSc[c4 + 1], sSh[c4 + 1]), 0.f);
        float f2 = fmaxf(fmaf(decf(u.z), sSc[c4 + 2], sSh[c4 + 2]), 0.f);
        float f3 = fmaxf(fmaf(decf(u.w), sSc[c4 + 3], sSh[c4 + 3]), 0.f);
        *(uint2*)&Ah[m * PA + 64 + c4] = make_uint2(h2u(__floats2half2_rn(f0, f1)),
                                                    h2u(__floats2half2_rn(f2, f3)));
    }
    // h0 half of Ah (k=0..63): y0 via tf32 MMA (bitwise = pass1), BN0+ReLU, fp16
    int g = lane >> 2, q = lane & 3, m0 = w * 16;
    {
        float acc0[8][4] = {};
        gemm0_mma(A, Wf0, m0, g, q, lane, acc0);
#pragma unroll
        for (int tt = 0; tt < 8; tt++) {
            int n = tt * 8 + q * 2;
            float h00 = fmaxf(fmaf(acc0[tt][0], sSc[n],     sSh[n]),     0.f);
            float h01 = fmaxf(fmaf(acc0[tt][1], sSc[n + 1], sSh[n + 1]), 0.f);
            float h10 = fmaxf(fmaf(acc0[tt][2], sSc[n],     sSh[n]),     0.f);
            float h11 = fmaxf(fmaf(acc0[tt][3], sSc[n + 1], sSh[n + 1]), 0.f);
            *(unsigned*)&Ah[(m0 + g) * PA + n]     = h2u(__floats2half2_rn(h00, h01));
            *(unsigned*)&Ah[(m0 + g + 8) * PA + n] = h2u(__floats2half2_rn(h10, h11));
        }
    }
    __syncthreads();

    // fp16 MMA via ldmatrix: warp w -> rows [w*16, w*16+16), all 64 n
    uint32_t lmaddr = (uint32_t)__cvta_generic_to_shared(
        &Ah[(m0 + (lane & 7) + (lane & 8)) * PA + (lane >> 4) * 8]);
    float acc[8][4] = {};
#pragma unroll
    for (int s = 0; s < 8; s++) {
        uint32_t a0, a1, a2, a3;
        asm volatile("ldmatrix.sync.aligned.m8n8.x4.shared.b16 {%0,%1,%2,%3}, [%4];"
                     : "=r"(a0), "=r"(a1), "=r"(a2), "=r"(a3)
                     : "r"(lmaddr + s * 32));
#pragma unroll
        for (int tt = 0; tt < 8; tt++) {
            uint2 b = Wf[(s * 8 + tt) * 32 + lane];
            mma16(acc[tt], a0, a1, a2, a3, b.x, b.y);
        }
    }
    __syncthreads();   // Ah dead -> Ys overlay safe
    spill(Ys, acc, m0, g, q);
    __syncthreads();
    segstat(Ys, sV, g_vm1, sp, sq, w, lane, t, 128);
}

// out = relu(sc1 * rawmax + sh1), vectorized, + coors tail; re-zero g_mean4
__global__ __launch_bounds__(256) void k_outfin(const int* __restrict__ coors,
                                                const float* __restrict__ gamma1,
                                                const float* __restrict__ beta1,
                                                float* __restrict__ out,
                                                int out_n, int do_coors) {
    __shared__ float sSc[64], sSh[64];
    int t = threadIdx.x;
    bn_finalize(128, gamma1, beta1, sSc, sSh, t);
    __syncthreads();
    int i4 = blockIdx.x * blockDim.x + t;
    if (i4 < NVOX) g_mean4[i4] = make_float4(0.f, 0.f, 0.f, 0.f);  // for next replay's hist
    if (i4 < NVOX * 16) {
        uint4 u = *(const uint4*)&g_vm1[(size_t)i4 * 4];
        int c = (i4 * 4) & 63;
        float4 r;
        r.x = fmaxf(fmaf(decf(u.x), sSc[c + 0], sSh[c + 0]), 0.f);
        r.y = fmaxf(fmaf(decf(u.y), sSc[c + 1], sSh[c + 1]), 0.f);
        r.z = fmaxf(fmaf(decf(u.z), sSc[c + 2], sSh[c + 2]), 0.f);
        r.w = fmaxf(fmaf(decf(u.w), sSc[c + 3], sSh[c + 3]), 0.f);
        if (i4 * 4 + 3 < out_n) {
            *(float4*)&out[(size_t)i4 * 4] = r;
        } else {
            if (i4 * 4 + 0 < out_n) out[i4 * 4 + 0] = r.x;
            if (i4 * 4 + 1 < out_n) out[i4 * 4 + 1] = r.y;
            if (i4 * 4 + 2 < out_n) out[i4 * 4 + 2] = r.z;
            if (i4 * 4 + 3 < out_n) out[i4 * 4 + 3] = r.w;
        }
    } else if (do_coors) {
        int j4 = i4 - NVOX * 16;
        if (j4 < NVOX) {
            int4 cc = ((const int4*)coors)[j4];
            float4 r = {(float)cc.x, (float)cc.y, (float)cc.z, (float)cc.w};
            *(float4*)&out[NVOX * 64 + (size_t)j4 * 4] = r;
        }
    }
}

// ---------------- launch ----------------
extern "C" void kernel_launch(void* const* d_in, const int* in_sizes, int n_in,
                              void* d_out, int out_size) {
    const float* feat   = (const float*)d_in[0];
    const float* W0     = (const float*)d_in[1];
    const float* gamma0 = (const float*)d_in[2];
    const float* beta0  = (const float*)d_in[3];
    const float* W1     = (const float*)d_in[4];
    const float* gamma1 = (const float*)d_in[5];
    const float* beta1  = (const float*)d_in[6];
    const int*   inv    = (const int*)d_in[7];
    const int*   coors  = (const int*)d_in[8];
    float* out = (float*)d_out;

    cudaFuncSetAttribute(k_pass2, cudaFuncAttributeMaxDynamicSharedMemorySize, P2_DSM);

    k_hist<<<(NPT + 255) / 256, 256>>>(feat, inv);
    k_scan1<<<NSCB, 1024>>>();
    k_scatter<<<(NPT / 4 + 255) / 256, 256>>>(inv);

    k_pass1<<<NB0, 256>>>(feat, coors, W0);
    k_pass2<<<NB0, 256, P2_DSM>>>(feat, coors, W0, W1, gamma0, beta0);

    int do_coors = (out_size >= NVOX * 64 + NVOX * 4) ? 1 : 0;
    k_outfin<<<(NVOX * 17 + 255) / 256, 256>>>(coors, gamma1, beta1, out, out_size, do_coors);
}

// round 17
// speedup vs baseline: 1.1572x; 1.0945x over previous
#include <cuda_runtime.h>
#include <cuda_fp16.h>
#include <cstdint>

#define NPT   400000
#define NVOX  100000
#define EPSBN 1e-3f
#define NB0   3125      // 128-point tiles
#define NBZ   782       // 128-voxel tiles for k_zv
#define NSCB  98
#define YP    133       // Ys pitch (odd word stride -> conflict-free column reads)
#define PA2   72        // Ah half-pitch (K=64 + 8 pad)
#define AP    20        // X10/A row pitch (words)

// ---------------- scratch ----------------
__device__ unsigned g_vm0[NVOX * 64];   // encoded raw voxel max, layer 0
__device__ unsigned g_vm1[NVOX * 64];   // encoded raw voxel max, layer 1
__device__ float    g_z[NVOX * 64];     // z = v0 @ W1b^T  (per-voxel layer-1 partial)
__device__ float4   g_mean4[NVOX];      // xyz sums, w = count
__device__ int      g_cur[NVOX];        // seeded with block-local offsets by scan1
__device__ int      g_bsum[NSCB];
__device__ int2     g_pv[NPT];          // (perm, vinv)
__device__ float    g_bns[256];         // [0:64) s0 [64:128) q0 [128:192) s1 [192:256) q1

// ---------------- helpers ----------------
__device__ __forceinline__ unsigned encf(float f) {
    int b = __float_as_int(f);
    return (b >= 0) ? ((unsigned)b | 0x80000000u) : ~(unsigned)b;
}
__device__ __forceinline__ float decf(unsigned u) {
    int b = (u & 0x80000000u) ? (int)(u & 0x7fffffffu) : ~(int)u;
    return __int_as_float(b);
}
__device__ __forceinline__ unsigned h2u(__half2 h) {
    return *reinterpret_cast<unsigned*>(&h);
}
__device__ __forceinline__ uint32_t tf32r(float x) {
    uint32_t u;
    asm("cvt.rna.tf32.f32 %0, %1;" : "=r"(u) : "f"(x));
    return u;
}
__device__ __forceinline__ void mma16(float c[4], uint32_t a0, uint32_t a1, uint32_t a2,
                                      uint32_t a3, uint32_t b0, uint32_t b1) {
    asm volatile("mma.sync.aligned.m16n8k16.row.col.f32.f16.f16.f32 "
                 "{%0,%1,%2,%3}, {%4,%5,%6,%7}, {%8,%9}, {%0,%1,%2,%3};"
                 : "+f"(c[0]), "+f"(c[1]), "+f"(c[2]), "+f"(c[3])
                 : "r"(a0), "r"(a1), "r"(a2), "r"(a3), "r"(b0), "r"(b1));
}
__device__ __forceinline__ void mma8(float c[4], uint32_t a0, uint32_t a1, uint32_t a2,
                                     uint32_t a3, uint32_t b0, uint32_t b1) {
    asm volatile("mma.sync.aligned.m16n8k8.row.col.f32.tf32.tf32.f32 "
                 "{%0,%1,%2,%3}, {%4,%5,%6,%7}, {%8,%9}, {%0,%1,%2,%3};"
                 : "+f"(c[0]), "+f"(c[1]), "+f"(c[2]), "+f"(c[3])
                 : "r"(a0), "r"(a1), "r"(a2), "r"(a3), "r"(b0), "r"(b1));
}

// Fused segmented max + BN stats over channel-major Ys[64][YP] (pass1, no z).
__device__ __forceinline__ void segstat(const float* Ys, const int* sV,
                                        unsigned* gdst, float (*spw)[64],
                                        float (*sqw)[64], int w, int lane, int t,
                                        int boff) {
    int rbeg = w * 16, rend = rbeg + 16;
    float sA = 0.f, qA = 0.f, sB = 0.f, qB = 0.f;
    for (int r = rbeg; r < rend; r++) {
        if (r > 0 && sV[r] == sV[r - 1]) continue;
        int e = r + 1;
        while (e < 128 && sV[e] == sV[r]) e++;
        float mA = -3.4e38f, mB = -3.4e38f;
        for (int x = r; x < e; x++) {
            float a = Ys[lane * YP + x];
            float b = Ys[(lane + 32) * YP + x];
            mA = fmaxf(mA, a); mB = fmaxf(mB, b);
            sA += a; qA += a * a;
            sB += b; qB += b * b;
        }
        unsigned* d = gdst + (size_t)sV[r] * 64;
        unsigned eA = encf(mA), eB = encf(mB);
        if (r == 0 || e == 128) {
            atomicMax(d + lane, eA);
            atomicMax(d + lane + 32, eB);
        } else {
            d[lane] = eA;
            d[lane + 32] = eB;
        }
    }
    spw[w][lane] = sA; spw[w][lane + 32] = sB;
    sqw[w][lane] = qA; sqw[w][lane + 32] = qB;
    __syncthreads();
    if (t < 64) {
        float s = 0.f, q = 0.f;
#pragma unroll
        for (int k = 0; k < 8; k++) { s += spw[k][t]; q += sqw[k][t]; }
        atomicAdd(&g_bns[boff + t], s);
        atomicAdd(&g_bns[boff + 64 + t], q);
    }
}

// pass2 variant: Ys holds Dh0 only; full D = Dh0 + z[voxel] with z constant per
// segment. max(D)=max(Dh0)+z; sum += sSeg + cnt*z; sumsq += qSeg + 2z*sSeg + cnt*z^2.
__device__ __forceinline__ void segstat_z(const float* Ys, const int* sV,
                                          unsigned* gdst, float (*spw)[64],
                                          float (*sqw)[64], int w, int lane, int t,
                                          int boff) {
    int rbeg = w * 16, rend = rbeg + 16;
    float sA = 0.f, qA = 0.f, sB = 0.f, qB = 0.f;
    for (int r = rbeg; r < rend; r++) {
        if (r > 0 && sV[r] == sV[r - 1]) continue;
        int e = r + 1;
        while (e < 128 && sV[e] == sV[r]) e++;
        const float* zr = g_z + (size_t)sV[r] * 64;
        float zA = zr[lane], zB = zr[lane + 32];
        float mA = -3.4e38f, mB = -3.4e38f;
        float sSa = 0.f, qSa = 0.f, sSb = 0.f, qSb = 0.f;
        for (int x = r; x < e; x++) {
            float a = Ys[lane * YP + x];
            float b = Ys[(lane + 32) * YP + x];
            mA = fmaxf(mA, a); mB = fmaxf(mB, b);
            sSa += a; qSa += a * a;
            sSb += b; qSb += b * b;
        }
        float cnt = (float)(e - r);
        sA += sSa + cnt * zA;
        qA += qSa + 2.f * zA * sSa + cnt * zA * zA;
        sB += sSb + cnt * zB;
        qB += qSb + 2.f * zB * sSb + cnt * zB * zB;
        unsigned* d = gdst + (size_t)sV[r] * 64;
        unsigned eA = encf(mA + zA), eB = encf(mB + zB);
        if (r == 0 || e == 128) {
            atomicMax(d + lane, eA);
            atomicMax(d + lane + 32, eB);
        } else {
            d[lane] = eA;
            d[lane + 32] = eB;
        }
    }
    spw[w][lane] = sA; spw[w][lane + 32] = sB;
    sqw[w][lane] = qA; sqw[w][lane + 32] = qB;
    __syncthreads();
    if (t < 64) {
        float s = 0.f, q = 0.f;
#pragma unroll
        for (int k = 0; k < 8; k++) { s += spw[k][t]; q += sqw[k][t]; }
        atomicAdd(&g_bns[boff + t], s);
        atomicAdd(&g_bns[boff + 64 + t], q);
    }
}

// D-fragment spill, channel-major
__device__ __forceinline__ void spill(float* Ys, const float acc[8][4],
                                      int m0, int g, int q) {
#pragma unroll
    for (int tt = 0; tt < 8; tt++) {
        int n = tt * 8 + q * 2;
        Ys[(n + 0) * YP + m0 + g]     = acc[tt][0];
        Ys[(n + 1) * YP + m0 + g]     = acc[tt][1];
        Ys[(n + 0) * YP + m0 + g + 8] = acc[tt][2];
        Ys[(n + 1) * YP + m0 + g + 8] = acc[tt][3];
    }
}

// Build the 10-feature row for point (base+t), tf32-rounded, row-major pitch AP.
__device__ __forceinline__ void build_a(float* A, int* sV, int base, int t,
                                        const float* __restrict__ feat,
                                        const int* __restrict__ coors) {
    int2 pv = g_pv[base + t];
    int p = pv.x, v = pv.y;
    sV[t] = v;
    float4 f = reinterpret_cast<const float4*>(feat)[p];
    float4 m = g_mean4[v];
    float ic = 1.f / m.w;
    int4 co = reinterpret_cast<const int4*>(coors)[v];
    float cx = (float)co.w * 0.2f + 0.1f;
    float cy = (float)co.z * 0.2f + 0.1f - 40.f;
    float cz = (float)co.y * 4.0f + 2.0f - 3.f;
    float xs[10] = {f.x, f.y, f.z,
                    f.x - m.x * ic, f.y - m.y * ic, f.z - m.z * ic,
                    f.x - cx, f.y - cy, f.z - cz, f.w};
    float* row = A + t * AP;
#pragma unroll
    for (int k = 0; k < 10; k++) row[k] = __uint_as_float(tf32r(xs[k]));
#pragma unroll
    for (int k = 10; k < 16; k++) row[k] = 0.f;
}

// Stage W0 tf32 B-fragments
__device__ __forceinline__ void stage_wf0(float2* Wf0, const float* __restrict__ W0,
                                          int t) {
#pragma unroll
    for (int it = 0; it < 2; it++) {
        int idx = it * 256 + t;
        int ln = idx & 31, st = idx >> 5;
        int s = st >> 3, tt = st & 7;
        int n = tt * 8 + (ln >> 2);
        int k = s * 8 + (ln & 3);
        float b0 = (k < 10) ? W0[n * 10 + k] : 0.f;
        float b1 = (k + 4 < 10) ? W0[n * 10 + k + 4] : 0.f;
        Wf0[idx] = make_float2(__uint_as_float(tf32r(b0)), __uint_as_float(tf32r(b1)));
    }
}

// Stage W1 fp16 B-fragments for K-range [kbase, kbase+64): 4 s-steps
__device__ __forceinline__ void stage_wf1(uint2* Wf, const float* __restrict__ W1,
                                          int kbase, int t) {
#pragma unroll
    for (int it = 0; it < 4; it++) {
        int idx = it * 256 + t;
        int ln = idx & 31, st = idx >> 5;
        int s = st >> 3, tt = st & 7;
        int n = tt * 8 + (ln >> 2);
        int k = kbase + s * 16 + (ln & 3) * 2;
        const float* wr = &W1[n * 128 + k];
        __half2 b0 = __floats2half2_rn(wr[0], wr[1]);
        __half2 b1 = __floats2half2_rn(wr[8], wr[9]);
        Wf[idx] = make_uint2(h2u(b0), h2u(b1));
    }
}

// fp16 MMA over Ah[128][PA2] (K=64): warp w -> rows [m0, m0+16), all 64 n
__device__ __forceinline__ void mma_h(const __half* Ah, const uint2* Wf,
                                      int m0, int lane, float acc[8][4]) {
    uint32_t lmaddr = (uint32_t)__cvta_generic_to_shared(
        &Ah[(m0 + (lane & 7) + (lane & 8)) * PA2 + (lane >> 4) * 8]);
#pragma unroll
    for (int s = 0; s < 4; s++) {
        uint32_t a0, a1, a2, a3;
        asm volatile("ldmatrix.sync.aligned.m8n8.x4.shared.b16 {%0,%1,%2,%3}, [%4];"
                     : "=r"(a0), "=r"(a1), "=r"(a2), "=r"(a3)
                     : "r"(lmaddr + s * 32));
#pragma unroll
        for (int tt = 0; tt < 8; tt++) {
            uint2 b = Wf[(s * 8 + tt) * 32 + lane];
            mma16(acc[tt], a0, a1, a2, a3, b.x, b.y);
        }
    }
}

// y0 fragments via tf32 MMA
__device__ __forceinline__ void gemm0_mma(const float* A, const float2* Wf0,
                                          int m0, int g, int q, int lane,
                                          float acc[8][4]) {
#pragma unroll
    for (int s = 0; s < 2; s++) {
        int k0 = s * 8;
        uint32_t a0 = __float_as_uint(A[(m0 + g) * AP + k0 + q]);
        uint32_t a1 = __float_as_uint(A[(m0 + g + 8) * AP + k0 + q]);
        uint32_t a2 = __float_as_uint(A[(m0 + g) * AP + k0 + q + 4]);
        uint32_t a3 = __float_as_uint(A[(m0 + g + 8) * AP + k0 + q + 4]);
#pragma unroll
        for (int tt = 0; tt < 8; tt++) {
            float2 b = Wf0[(s * 8 + tt) * 32 + lane];
            mma8(acc[tt], a0, a1, a2, a3, __float_as_uint(b.x), __float_as_uint(b.y));
        }
    }
}

// per-block BN finalize from g_bns
__device__ __forceinline__ void bn_finalize(int boff, const float* __restrict__ gamma,
                                            const float* __restrict__ beta,
                                            float* sSc, float* sSh, int t) {
    if (t < 64) {
        double mu = (double)g_bns[boff + t] / (double)NPT;
        double var = (double)g_bns[boff + 64 + t] / (double)NPT - mu * mu;
        float sc = gamma[t] * rsqrtf((float)var + EPSBN);
        sSc[t] = sc;
        sSh[t] = beta[t] - (float)mu * sc;
    }
}

// ---------------- hist ----------------
__global__ void k_hist(const float* __restrict__ feat, const int* __restrict__ inv) {
    int p = blockIdx.x * blockDim.x + threadIdx.x;
    if (p >= NPT) return;
    float4 f = reinterpret_cast<const float4*>(feat)[p];
    int v = inv[p];
    asm volatile("red.global.add.v4.f32 [%0], {%1, %2, %3, %4};"
                 :: "l"(&g_mean4[v]), "f"(f.x), "f"(f.y), "f"(f.z), "f"(1.0f)
                 : "memory");
}

// ---------------- counts scan (warp-shuffle) ----------------
__global__ __launch_bounds__(1024) void k_scan1() {
    __shared__ int wsum[32];
    int i = blockIdx.x * 1024 + threadIdx.x;
    int v = (i < NVOX) ? (int)g_mean4[i].w : 0;
    int lane = threadIdx.x & 31, wid = threadIdx.x >> 5;
    int x = v;
#pragma unroll
    for (int d = 1; d < 32; d <<= 1) {
        int y = __shfl_up_sync(0xffffffffu, x, d);
        if (lane >= d) x += y;
    }
    if (lane == 31) wsum[wid] = x;
    __syncthreads();
    if (wid == 0) {
        int y = wsum[lane];
#pragma unroll
        for (int d = 1; d < 32; d <<= 1) {
            int z = __shfl_up_sync(0xffffffffu, y, d);
            if (lane >= d) y += z;
        }
        wsum[lane] = y;
    }
    __syncthreads();
    int pre = (wid > 0) ? wsum[wid - 1] : 0;
    if (i < NVOX) g_cur[i] = pre + x - v;
    if (threadIdx.x == 1023) g_bsum[blockIdx.x] = pre + x;
}

// ---------------- scatter ----------------
__global__ __launch_bounds__(256) void k_scatter(const int* __restrict__ inv) {
    __shared__ int pre[128];
    int t = threadIdx.x;
    if (t < 128) pre[t] = (t < NSCB) ? g_bsum[t] : 0;
    __syncthreads();
    for (int d = 1; d < 128; d <<= 1) {
        int x = (t >= d && t < 128) ? pre[t - d] : 0;
        __syncthreads();
        if (t < 128) pre[t] += x;
        __syncthreads();
    }
    int i = blockIdx.x * blockDim.x + t;
    if (i < 256) g_bns[i] = 0.f;       // reset BN accumulators for this replay
    int p0 = i * 4;
    if (p0 >= NPT) return;
    int4 vv = ((const int4*)inv)[i];
    int r0 = atomicAdd(&g_cur[vv.x], 1);
    int r1 = atomicAdd(&g_cur[vv.y], 1);
    int r2 = atomicAdd(&g_cur[vv.z], 1);
    int r3 = atomicAdd(&g_cur[vv.w], 1);
    int b0 = vv.x >> 10, b1 = vv.y >> 10, b2 = vv.z >> 10, b3 = vv.w >> 10;
    g_pv[r0 + (b0 ? pre[b0 - 1] : 0)] = make_int2(p0 + 0, vv.x);
    g_pv[r1 + (b1 ? pre[b1 - 1] : 0)] = make_int2(p0 + 1, vv.y);
    g_pv[r2 + (b2 ? pre[b2 - 1] : 0)] = make_int2(p0 + 2, vv.z);
    g_pv[r3 + (b3 ? pre[b3 - 1] : 0)] = make_int2(p0 + 3, vv.w);
}

// ---------------- pass1: y0 via tf32 MMA -> stats + raw voxel max ----------------
__global__ __launch_bounds__(256) void k_pass1(const float* __restrict__ feat,
                                               const int* __restrict__ coors,
                                               const float* __restrict__ W0) {
    __shared__ float S[64 * YP];
    __shared__ int   sV[128];
    __shared__ float sp[8][64], sq[8][64];
    float*  A   = S;
    float2* Wf0 = (float2*)(S + 128 * AP);
    float*  Ys  = S;
    int t = threadIdx.x, lane = t & 31, w = t >> 5;
    int base = blockIdx.x * 128;
    if (t < 128) build_a(A, sV, base, t, feat, coors);
    stage_wf0(Wf0, W0, t);
    __syncthreads();
    int g = lane >> 2, q = lane & 3, m0 = w * 16;
    float acc[8][4] = {};
    gemm0_mma(A, Wf0, m0, g, q, lane, acc);
    __syncthreads();
    spill(Ys, acc, m0, g, q);
    __syncthreads();
    segstat(Ys, sV, g_vm0, sp, sq, w, lane, t, 0);
}

// ---------------- k_zv: z = relu(bn0(vm0)) @ W1b^T  per voxel ----------------
__global__ __launch_bounds__(256) void k_zv(const float* __restrict__ W1,
                                            const float* __restrict__ gamma0,
                                            const float* __restrict__ beta0) {
    __shared__ __half Ah[128 * PA2];
    __shared__ uint2  Wfb[1024];
    __shared__ float  sSc[64], sSh[64];
    int t = threadIdx.x, lane = t & 31, w = t >> 5;
    int base = blockIdx.x * 128;
    bn_finalize(0, gamma0, beta0, sSc, sSh, t);
    stage_wf1(Wfb, W1, 64, t);
    __syncthreads();
    // decode vm0 -> v0 fp16 rows (one row per voxel)
#pragma unroll
    for (int it = 0; it < 8; it++) {
        int idx = it * 256 + t;
        int m = idx >> 4, c4 = (idx & 15) * 4;
        int vb = base + m;
        if (vb >= NVOX) vb = NVOX - 1;
        uint4 u = *(const uint4*)&g_vm0[(size_t)vb * 64 + c4];
        float f0 = fmaxf(fmaf(decf(u.x), sSc[c4 + 0], sSh[c4 + 0]), 0.f);
        float f1 = fmaxf(fmaf(decf(u.y), sSc[c4 + 1], sSh[c4 + 1]), 0.f);
        float f2 = fmaxf(fmaf(decf(u.z), sSc[c4 + 2], sSh[c4 + 2]), 0.f);
        float f3 = fmaxf(fmaf(decf(u.w), sSc[c4 + 3], sSh[c4 + 3]), 0.f);
        *(uint2*)&Ah[m * PA2 + c4] = make_uint2(h2u(__floats2half2_rn(f0, f1)),
                                                h2u(__floats2half2_rn(f2, f3)));
    }
    __syncthreads();
    int g = lane >> 2, q = lane & 3, m0 = w * 16;
    float acc[8][4] = {};
    mma_h(Ah, Wfb, m0, lane, acc);
    // write z, coalesced float2 stores
#pragma unroll
    for (int tt = 0; tt < 8; tt++) {
        int n = tt * 8 + q * 2;
        int v0r = base + m0 + g, v1r = base + m0 + g + 8;
        if (v0r < NVOX) *(float2*)&g_z[(size_t)v0r * 64 + n] = make_float2(acc[tt][0], acc[tt][1]);
        if (v1r < NVOX) *(float2*)&g_z[(size_t)v1r * 64 + n] = make_float2(acc[tt][2], acc[tt][3]);
    }
}

// ---------------- pass2: h0 via tf32 MMA -> fp16 MMA (K=64) -> segstat_z ----------------
// static smem layout (bytes):
//   [0, 18432)      Ah half[128][PA2]
//   [18432, 26624)  Wf uint2[1024]     (W1a fp16 fragments)
//   [26624, 36864)  A float[128*AP]    (tf32 X10)
//   [36864, 40960)  Wf0 float2[512]
//   Ys[64*YP] (34048 B) overlays from 0 after the main MMA
__global__ __launch_bounds__(256) void k_pass2(const float* __restrict__ feat,
                                               const int* __restrict__ coors,
                                               const float* __restrict__ W0,
                                               const float* __restrict__ W1,
                                               const float* __restrict__ gamma0,
                                               const float* __restrict__ beta0) {
    __shared__ __align__(16) char smem[40960];
    __half* Ah  = (__half*)smem;
    uint2*  Wf  = (uint2*)(smem + 18432);
    float*  A   = (float*)(smem + 26624);
    float2* Wf0 = (float2*)(smem + 36864);
    float*  Ys  = (float*)smem;
    __shared__ int   sV[128];
    __shared__ float sSc[64], sSh[64];
    __shared__ float sp[8][64], sq[8][64];

    int t = threadIdx.x, lane = t & 31, w = t >> 5;
    int base = blockIdx.x * 128;

    if (t < 128) build_a(A, sV, base, t, feat, coors);
    bn_finalize(0, gamma0, beta0, sSc, sSh, t);
    stage_wf0(Wf0, W0, t);
    stage_wf1(Wf, W1, 0, t);
    __syncthreads();

    // h0 rows: y0 via tf32 MMA (bitwise = pass1), BN0+ReLU, fp16
    int g = lane >> 2, q = lane & 3, m0 = w * 16;
    {
        float acc0[8][4] = {};
        gemm0_mma(A, Wf0, m0, g, q, lane, acc0);
#pragma unroll
        for (int tt = 0; tt < 8; tt++) {
            int n = tt * 8 + q * 2;
            float h00 = fmaxf(fmaf(acc0[tt][0], sSc[n],     sSh[n]),     0.f);
            float h01 = fmaxf(fmaf(acc0[tt][1], sSc[n + 1], sSh[n + 1]), 0.f);
            float h10 = fmaxf(fmaf(acc0[tt][2], sSc[n],     sSh[n]),     0.f);
            float h11 = fmaxf(fmaf(acc0[tt][3], sSc[n + 1], sSh[n + 1]), 0.f);
            *(unsigned*)&Ah[(m0 + g) * PA2 + n]     = h2u(__floats2half2_rn(h00, h01));
            *(unsigned*)&Ah[(m0 + g + 8) * PA2 + n] = h2u(__floats2half2_rn(h10, h11));
        }
    }
    __syncthreads();

    float acc[8][4] = {};
    mma_h(Ah, Wf, m0, lane, acc);
    __syncthreads();   // Ah/Wf/A/Wf0 dead -> Ys overlay safe
    spill(Ys, acc, m0, g, q);
    __syncthreads();
    segstat_z(Ys, sV, g_vm1, sp, sq, w, lane, t, 128);
}

// out = relu(sc1 * rawmax + sh1), vectorized, + coors tail; re-zero g_mean4
__global__ __launch_bounds__(256) void k_outfin(const int* __restrict__ coors,
                                                const float* __restrict__ gamma1,
                                                const float* __restrict__ beta1,
                                                float* __restrict__ out,
                                                int out_n, int do_coors) {
    __shared__ float sSc[64], sSh[64];
    int t = threadIdx.x;
    bn_finalize(128, gamma1, beta1, sSc, sSh, t);
    __syncthreads();
    int i4 = blockIdx.x * blockDim.x + t;
    if (i4 < NVOX) g_mean4[i4] = make_float4(0.f, 0.f, 0.f, 0.f);  // for next replay's hist
    if (i4 < NVOX * 16) {
        uint4 u = *(const uint4*)&g_vm1[(size_t)i4 * 4];
        int c = (i4 * 4) & 63;
        float4 r;
        r.x = fmaxf(fmaf(decf(u.x), sSc[c + 0], sSh[c + 0]), 0.f);
        r.y = fmaxf(fmaf(decf(u.y), sSc[c + 1], sSh[c + 1]), 0.f);
        r.z = fmaxf(fmaf(decf(u.z), sSc[c + 2], sSh[c + 2]), 0.f);
        r.w = fmaxf(fmaf(decf(u.w), sSc[c + 3], sSh[c + 3]), 0.f);
        if (i4 * 4 + 3 < out_n) {
            *(float4*)&out[(size_t)i4 * 4] = r;
        } else {
            if (i4 * 4 + 0 < out_n) out[i4 * 4 + 0] = r.x;
            if (i4 * 4 + 1 < out_n) out[i4 * 4 + 1] = r.y;
            if (i4 * 4 + 2 < out_n) out[i4 * 4 + 2] = r.z;
            if (i4 * 4 + 3 < out_n) out[i4 * 4 + 3] = r.w;
        }
    } else if (do_coors) {
        int j4 = i4 - NVOX * 16;
        if (j4 < NVOX) {
            int4 cc = ((const int4*)coors)[j4];
            float4 r = {(float)cc.x, (float)cc.y, (float)cc.z, (float)cc.w};
            *(float4*)&out[NVOX * 64 + (size_t)j4 * 4] = r;
        }
    }
}

// ---------------- launch ----------------
extern "C" void kernel_launch(void* const* d_in, const int* in_sizes, int n_in,
                              void* d_out, int out_size) {
    const float* feat   = (const float*)d_in[0];
    const float* W0     = (const float*)d_in[1];
    const float* gamma0 = (const float*)d_in[2];
    const float* beta0  = (const float*)d_in[3];
    const float* W1     = (const float*)d_in[4];
    const float* gamma1 = (const float*)d_in[5];
    const float* beta1  = (const float*)d_in[6];
    const int*   inv    = (const int*)d_in[7];
    const int*   coors  = (const int*)d_in[8];
    float* out = (float*)d_out;

    k_hist<<<(NPT + 255) / 256, 256>>>(feat, inv);
    k_scan1<<<NSCB, 1024>>>();
    k_scatter<<<(NPT / 4 + 255) / 256, 256>>>(inv);

    k_pass1<<<NB0, 256>>>(feat, coors, W0);
    k_zv<<<NBZ, 256>>>(W1, gamma0, beta0);
    k_pass2<<<NB0, 256>>>(feat, coors, W0, W1, gamma0, beta0);

    int do_coors = (out_size >= NVOX * 64 + NVOX * 4) ? 1 : 0;
    k_outfin<<<(NVOX * 17 + 255) / 256, 256>>>(coors, gamma1, beta1, out, out_size, do_coors);
}